// round 12
// baseline (speedup 1.0000x reference)
#include <cuda_runtime.h>

#define A_COEF 0.01f
#define B_COEF 4.81f
#define C_COEF 0.0f
#define OOB_COST 3.0f

#define ROWS_PER_THREAD 8
#define BLOCK 512
#define PERSIST_BLOCKS 444   // 148 SMs x 3 resident CTAs @ 512 thr (regs=23)

__device__ __forceinline__ float penal(float v) {
    float cost = C_COEF + A_COEF * __expf(B_COEF * (1.0f + v));
    bool in_bounds = (v >= 0.0f) && (v <= 1.0f);
    return in_bounds ? cost : OOB_COST;
}

__global__ void __launch_bounds__(BLOCK) penalizer_kernel(
    const float* __restrict__ X, float* __restrict__ out, int n_rows)
{
    // Persistent grid-stride over tiles of BLOCK*ROWS_PER_THREAD rows.
    // Inner pattern identical to the proven optimum: lanes read 32 consecutive
    // rows per iteration (nL=8 lines/warp-LDG), 8 front-batched __ldcs loads,
    // write-through stores.
    const long long tileRows = (long long)BLOCK * ROWS_PER_THREAD;
    const long long nTiles = (n_rows + tileRows - 1) / tileRows;

    for (long long tile = blockIdx.x; tile < nTiles; tile += gridDim.x) {
        long long blockBase = tile * tileRows;

        if (blockBase + tileRows <= n_rows) {
            float v[ROWS_PER_THREAD];
            #pragma unroll
            for (int j = 0; j < ROWS_PER_THREAD; ++j) {
                long long row = blockBase + j * BLOCK + threadIdx.x;
                v[j] = __ldcs(X + row * 8 + 7);
            }
            #pragma unroll
            for (int j = 0; j < ROWS_PER_THREAD; ++j) {
                long long row = blockBase + j * BLOCK + threadIdx.x;
                __stwt(out + row, penal(v[j]));
            }
        } else {
            // tail tile (not hit when n_rows % tileRows == 0)
            for (int j = 0; j < ROWS_PER_THREAD; ++j) {
                long long row = blockBase + j * BLOCK + threadIdx.x;
                if (row < n_rows) {
                    out[row] = penal(__ldcs(X + row * 8 + 7));
                }
            }
        }
    }
}

extern "C" void kernel_launch(void* const* d_in, const int* in_sizes, int n_in,
                              void* d_out, int out_size)
{
    const float* X = (const float*)d_in[0];
    float* out = (float*)d_out;
    int n_rows = in_sizes[0] / 8;          // [N, 8] fp32
    long long tileRows = (long long)BLOCK * ROWS_PER_THREAD;
    long long nTiles = (n_rows + tileRows - 1) / tileRows;
    int grid = (int)(nTiles < PERSIST_BLOCKS ? nTiles : PERSIST_BLOCKS);
    penalizer_kernel<<<grid, BLOCK>>>(X, out, n_rows);
}

// round 14
// speedup vs baseline: 1.0616x; 1.0616x over previous
#include <cuda_runtime.h>

#define A_COEF 0.01f
#define B_COEF 4.81f
#define C_COEF 0.0f
#define OOB_COST 3.0f

#define ROWS_PER_THREAD 8
#define BLOCK 512

__device__ __forceinline__ float penal(float v) {
    float cost = C_COEF + A_COEF * __expf(B_COEF * (1.0f + v));
    bool in_bounds = (v >= 0.0f) && (v <= 1.0f);
    return in_bounds ? cost : OOB_COST;
}

__global__ void __launch_bounds__(BLOCK) penalizer_kernel(
    const float* __restrict__ X, float* __restrict__ out, int n_rows)
{
    // FINAL (R8 config — measured optimum across the full sweep):
    //  - Block-interleaved addressing: each iteration j, a warp's 32 lanes read
    //    32 CONSECUTIVE rows (1024B contiguous) -> 8 x 128B lines per warp-LDG,
    //    minimizing L1tex wavefronts (the R4 4x win vs per-thread-contiguous).
    //  - 8 front-batched __ldcs streaming loads per thread (MLP sweet spot;
    //    4 and 16 both measured slower).
    //  - __stwt write-through stores: keeps the 64MB write stream out of L2's
    //    dirty set (best kernel time of stcs/stwt).
    //  - BLOCK=512 (256: 83.2us, 512: 81.1us, 1024: 83.0us kernel time).
    //  - Classic launch (persistent grid-stride regressed: regs 23->32,
    //    occ 79->63%).
    // Kernel time ~81us = within ~1% of the 576MB compulsory-traffic floor
    // (one 32B DRAM sector per 32B row is irreducible) at ~7.1 TB/s.
    long long blockBase = (long long)blockIdx.x * (BLOCK * ROWS_PER_THREAD);

    if (blockBase + BLOCK * ROWS_PER_THREAD <= n_rows) {
        float v[ROWS_PER_THREAD];
        #pragma unroll
        for (int j = 0; j < ROWS_PER_THREAD; ++j) {
            long long row = blockBase + j * BLOCK + threadIdx.x;
            v[j] = __ldcs(X + row * 8 + 7);
        }
        #pragma unroll
        for (int j = 0; j < ROWS_PER_THREAD; ++j) {
            long long row = blockBase + j * BLOCK + threadIdx.x;
            __stwt(out + row, penal(v[j]));
        }
    } else {
        // tail block (not hit when n_rows % (BLOCK*ROWS_PER_THREAD) == 0)
        for (int j = 0; j < ROWS_PER_THREAD; ++j) {
            long long row = blockBase + j * BLOCK + threadIdx.x;
            if (row < n_rows) {
                out[row] = penal(__ldcs(X + row * 8 + 7));
            }
        }
    }
}

extern "C" void kernel_launch(void* const* d_in, const int* in_sizes, int n_in,
                              void* d_out, int out_size)
{
    const float* X = (const float*)d_in[0];
    float* out = (float*)d_out;
    int n_rows = in_sizes[0] / 8;          // [N, 8] fp32
    long long rows_per_block = (long long)BLOCK * ROWS_PER_THREAD;
    int grid = (int)((n_rows + rows_per_block - 1) / rows_per_block);
    penalizer_kernel<<<grid, BLOCK>>>(X, out, n_rows);
}

// round 15
// speedup vs baseline: 1.0651x; 1.0033x over previous
#include <cuda_runtime.h>

#define A_COEF 0.01f
#define B_COEF 4.81f
#define C_COEF 0.0f
#define OOB_COST 3.0f

#define ROWS_PER_THREAD 8
#define BLOCK 512

__device__ __forceinline__ float penal(float v) {
    float cost = C_COEF + A_COEF * __expf(B_COEF * (1.0f + v));
    bool in_bounds = (v >= 0.0f) && (v <= 1.0f);
    return in_bounds ? cost : OOB_COST;
}

__global__ void __launch_bounds__(BLOCK) penalizer_kernel(
    const float* __restrict__ X, float* __restrict__ out, int n_rows)
{
    // R15 isolation: BLOCK=512 geometry (measured optimum) with __stcs
    // (streaming write-back) stores — the one untested cell of the
    // (BLOCK x store-policy) matrix. Everything else identical to R8:
    //  - Block-interleaved addressing: warp's 32 lanes read 32 CONSECUTIVE
    //    rows (1024B contiguous) -> 8 x 128B lines per warp-LDG.
    //  - 8 front-batched __ldcs streaming loads per thread.
    long long blockBase = (long long)blockIdx.x * (BLOCK * ROWS_PER_THREAD);

    if (blockBase + BLOCK * ROWS_PER_THREAD <= n_rows) {
        float v[ROWS_PER_THREAD];
        #pragma unroll
        for (int j = 0; j < ROWS_PER_THREAD; ++j) {
            long long row = blockBase + j * BLOCK + threadIdx.x;
            v[j] = __ldcs(X + row * 8 + 7);
        }
        #pragma unroll
        for (int j = 0; j < ROWS_PER_THREAD; ++j) {
            long long row = blockBase + j * BLOCK + threadIdx.x;
            __stcs(out + row, penal(v[j]));
        }
    } else {
        // tail block (not hit when n_rows % (BLOCK*ROWS_PER_THREAD) == 0)
        for (int j = 0; j < ROWS_PER_THREAD; ++j) {
            long long row = blockBase + j * BLOCK + threadIdx.x;
            if (row < n_rows) {
                out[row] = penal(__ldcs(X + row * 8 + 7));
            }
        }
    }
}

extern "C" void kernel_launch(void* const* d_in, const int* in_sizes, int n_in,
                              void* d_out, int out_size)
{
    const float* X = (const float*)d_in[0];
    float* out = (float*)d_out;
    int n_rows = in_sizes[0] / 8;          // [N, 8] fp32
    long long rows_per_block = (long long)BLOCK * ROWS_PER_THREAD;
    int grid = (int)((n_rows + rows_per_block - 1) / rows_per_block);
    penalizer_kernel<<<grid, BLOCK>>>(X, out, n_rows);
}